// round 14
// baseline (speedup 1.0000x reference)
#include <cuda_runtime.h>

#define BB  2
#define CH  8
#define AM  8
#define NHH 8
#define FF  256
#define WW  768
#define DHH 32
#define CA  16   // CH + AM

#define YSZ (BB*AM*FF*WW)         // 3,145,728
#define OUT_ELEMS (BB*CH*FF*WW)   // 3,145,728

typedef unsigned long long ull;

// ---- scratch (static device memory; allocation is forbidden) ----
__device__ float g_yq[YSZ];
__device__ float g_yk[YSZ];
__device__ float g_yv[YSZ];
__device__ float g_q [YSZ];   // (b,m, g=h*32+d, w)
__device__ float g_k [YSZ];
__device__ float g_v [YSZ];
__device__ float g_a [YSZ];   // attention result (b,m,f,w)
__device__ float g_o1[BB*CA*FF*WW];
__device__ float2 g_cs[16*WW];  // RoPE table: [e][w] -> (cos, sin)

// conv weights in constant memory
__constant__ float c_qcw[AM*CH*9];
__constant__ float c_kcw[AM*CH*9];
__constant__ float c_vcw[AM*CH*9];
__constant__ float c_qcb[AM];
__constant__ float c_kcb[AM];
__constant__ float c_vcb[AM];

// ---------- packed f32x2 helpers ----------
__device__ __forceinline__ ull bc2(float v) {
    ull r; asm("mov.b64 %0, {%1, %1};" : "=l"(r) : "f"(v)); return r;
}
__device__ __forceinline__ ull pk2(float lo, float hi) {
    ull r; asm("mov.b64 %0, {%1, %2};" : "=l"(r) : "f"(lo), "f"(hi)); return r;
}
__device__ __forceinline__ void fma2(ull& d, ull a, ull b) {
    asm("fma.rn.f32x2 %0, %1, %2, %0;" : "+l"(d) : "l"(a), "l"(b));
}
__device__ __forceinline__ float2 up2(ull v) {
    float lo, hi; asm("mov.b64 {%0, %1}, %2;" : "=f"(lo), "=f"(hi) : "l"(v));
    return make_float2(lo, hi);
}

// =====================================================================
// K0: RoPE cos/sin table init
// =====================================================================
__global__ void cs_init_kernel()
{
    int idx = blockIdx.x * 256 + threadIdx.x;
    if (idx >= 16*WW) return;
    int e = idx / WW, w = idx % WW;
    float inv = expf(-(float)(2*e) * (9.210340371976184f / 32.0f));
    float s, c;
    sincosf((float)w * inv, &s, &c);
    g_cs[idx] = make_float2(c, s);
}

// =====================================================================
// K1: 3x3 conv + bias for q,k,v. 2 outputs/thread via f32x2.
// =====================================================================
__global__ __launch_bounds__(384)
void conv_kernel(const float* __restrict__ x)
{
    int tid = threadIdx.x;
    int w0  = tid * 2;
    int f   = blockIdx.x;
    int bm  = blockIdx.y;
    int m = bm % AM, b = bm / AM;

    ull aq = bc2(c_qcb[m]), ak = bc2(c_kcb[m]), av = bc2(c_vcb[m]);

    #pragma unroll
    for (int ci = 0; ci < CH; ci++) {
        const float* xp = x + (size_t)((b*CH + ci)*FF) * WW;
        #pragma unroll
        for (int kh = 0; kh < 3; kh++) {
            int ff = f + kh - 1;
            if (ff < 0 || ff >= FF) continue;
            const float* xr = xp + ff*WW;
            float xm1 = (w0 > 0)      ? xr[w0-1] : 0.f;
            float2 xc = *reinterpret_cast<const float2*>(&xr[w0]);
            float x2  = (w0+2 < WW)   ? xr[w0+2] : 0.f;
            ull pm = pk2(xm1, xc.x);
            ull p0 = pk2(xc.x, xc.y);
            ull pp = pk2(xc.y, x2);
            int wb = m*72 + ci*9 + kh*3;
            fma2(aq, pm, bc2(c_qcw[wb+0])); fma2(aq, p0, bc2(c_qcw[wb+1])); fma2(aq, pp, bc2(c_qcw[wb+2]));
            fma2(ak, pm, bc2(c_kcw[wb+0])); fma2(ak, p0, bc2(c_kcw[wb+1])); fma2(ak, pp, bc2(c_kcw[wb+2]));
            fma2(av, pm, bc2(c_vcw[wb+0])); fma2(av, p0, bc2(c_vcw[wb+1])); fma2(av, pp, bc2(c_vcw[wb+2]));
        }
    }
    int oid = ((b*AM + m)*FF + f)*WW + w0;
    float2 q2 = up2(aq), k2 = up2(ak), v2 = up2(av);
    *reinterpret_cast<float2*>(&g_yq[oid]) = q2;
    *reinterpret_cast<float2*>(&g_yk[oid]) = k2;
    *reinterpret_cast<float2*>(&g_yv[oid]) = v2;
}

// =====================================================================
// K2: positionwise linear, 128x128 tile, 8x8 microtile, f32x2,
// register-prefetched k-slices.
// =====================================================================
__global__ __launch_bounds__(256, 2)
void pw_kernel(const float* __restrict__ qpw,
               const float* __restrict__ kpw,
               const float* __restrict__ vpw)
{
    int z  = blockIdx.z;
    int p  = z / (BB*AM);     // 0=q 1=k 2=v
    int bm = z % (BB*AM);
    int m  = bm % AM;

    const float* A  = (p == 0 ? qpw : (p == 1 ? kpw : vpw)) + (size_t)m*FF*FF;      // (g,f)
    const float* Bm = (p == 0 ? g_yq : (p == 1 ? g_yk : g_yv)) + (size_t)bm*FF*WW;  // (f,w)
    float*      Out = (p == 0 ? g_q : (p == 1 ? g_k : g_v)) + (size_t)bm*FF*WW;     // (g,w)

    __shared__ float  As[16][132];   // [f][g]
    __shared__ float  Bs[16][132];   // [f][w]
    __shared__ float2 Ts[16][128];   // [e][w-local]

    int g0 = blockIdx.x * 128, w0 = blockIdx.y * 128;
    int tid = threadIdx.x;
    int ty = tid >> 4, tx = tid & 15;

    if (p < 2) {
        #pragma unroll
        for (int it = 0; it < 8; it++) {
            int li = tid + it*256;
            int e = li >> 7, tw = li & 127;
            Ts[e][tw] = g_cs[e*WW + w0 + tw];
        }
    }

    int la_r[2], la_c[2], lb_r[2], lb_c[2];
    #pragma unroll
    for (int it = 0; it < 2; it++) {
        int li = tid + it*256;
        la_r[it] = li >> 2;  la_c[it] = (li & 3) * 4;
        lb_r[it] = li >> 5;  lb_c[it] = (li & 31) * 4;
    }

    float4 ra[2], rb[2];
    #pragma unroll
    for (int it = 0; it < 2; it++) {
        ra[it] = *reinterpret_cast<const float4*>(&A[(size_t)(g0 + la_r[it])*FF + la_c[it]]);
        rb[it] = *reinterpret_cast<const float4*>(&Bm[(size_t)lb_r[it]*WW + w0 + lb_c[it]]);
    }

    ull acc2[8][4];
    #pragma unroll
    for (int i = 0; i < 8; i++)
        #pragma unroll
        for (int j = 0; j < 4; j++) acc2[i][j] = 0ull;

    for (int f0 = 0; f0 < FF; f0 += 16) {
        if (f0) __syncthreads();
        #pragma unroll
        for (int it = 0; it < 2; it++) {
            As[la_c[it]+0][la_r[it]] = ra[it].x;
            As[la_c[it]+1][la_r[it]] = ra[it].y;
            As[la_c[it]+2][la_r[it]] = ra[it].z;
            As[la_c[it]+3][la_r[it]] = ra[it].w;
            *reinterpret_cast<float4*>(&Bs[lb_r[it]][lb_c[it]]) = rb[it];
        }
        __syncthreads();
        if (f0 + 16 < FF) {
            int f1 = f0 + 16;
            #pragma unroll
            for (int it = 0; it < 2; it++) {
                ra[it] = *reinterpret_cast<const float4*>(&A[(size_t)(g0 + la_r[it])*FF + f1 + la_c[it]]);
                rb[it] = *reinterpret_cast<const float4*>(&Bm[(size_t)(f1 + lb_r[it])*WW + w0 + lb_c[it]]);
            }
        }

        #pragma unroll
        for (int kk = 0; kk < 16; kk++) {
            float4 a0 = *reinterpret_cast<const float4*>(&As[kk][ty*8]);
            float4 a1 = *reinterpret_cast<const float4*>(&As[kk][ty*8 + 4]);
            ulonglong2 b0 = *reinterpret_cast<const ulonglong2*>(&Bs[kk][tx*8]);
            ulonglong2 b1 = *reinterpret_cast<const ulonglong2*>(&Bs[kk][tx*8 + 4]);
            ull av0 = bc2(a0.x), av1 = bc2(a0.y), av2 = bc2(a0.z), av3 = bc2(a0.w);
            ull av4 = bc2(a1.x), av5 = bc2(a1.y), av6 = bc2(a1.z), av7 = bc2(a1.w);
            fma2(acc2[0][0], av0, b0.x); fma2(acc2[0][1], av0, b0.y); fma2(acc2[0][2], av0, b1.x); fma2(acc2[0][3], av0, b1.y);
            fma2(acc2[1][0], av1, b0.x); fma2(acc2[1][1], av1, b0.y); fma2(acc2[1][2], av1, b1.x); fma2(acc2[1][3], av1, b1.y);
            fma2(acc2[2][0], av2, b0.x); fma2(acc2[2][1], av2, b0.y); fma2(acc2[2][2], av2, b1.x); fma2(acc2[2][3], av2, b1.y);
            fma2(acc2[3][0], av3, b0.x); fma2(acc2[3][1], av3, b0.y); fma2(acc2[3][2], av3, b1.x); fma2(acc2[3][3], av3, b1.y);
            fma2(acc2[4][0], av4, b0.x); fma2(acc2[4][1], av4, b0.y); fma2(acc2[4][2], av4, b1.x); fma2(acc2[4][3], av4, b1.y);
            fma2(acc2[5][0], av5, b0.x); fma2(acc2[5][1], av5, b0.y); fma2(acc2[5][2], av5, b1.x); fma2(acc2[5][3], av5, b1.y);
            fma2(acc2[6][0], av6, b0.x); fma2(acc2[6][1], av6, b0.y); fma2(acc2[6][2], av6, b1.x); fma2(acc2[6][3], av6, b1.y);
            fma2(acc2[7][0], av7, b0.x); fma2(acc2[7][1], av7, b0.y); fma2(acc2[7][2], av7, b1.x); fma2(acc2[7][3], av7, b1.y);
        }
    }

    if (p == 2) {
        #pragma unroll
        for (int i = 0; i < 8; i++) {
            int g = g0 + ty*8 + i;
            float r_[8];
            #pragma unroll
            for (int j = 0; j < 4; j++) {
                float2 f2 = up2(acc2[i][j]);
                r_[2*j] = f2.x; r_[2*j+1] = f2.y;
            }
            float* op = &Out[(size_t)g*WW + w0 + tx*8];
            *reinterpret_cast<float4*>(op)     = make_float4(r_[0], r_[1], r_[2], r_[3]);
            *reinterpret_cast<float4*>(op + 4) = make_float4(r_[4], r_[5], r_[6], r_[7]);
        }
    } else {
        #pragma unroll
        for (int ip = 0; ip < 4; ip++) {
            int g = g0 + ty*8 + ip*2;
            int e = (g & 31) >> 1;
            float re[8], ro[8];
            #pragma unroll
            for (int j = 0; j < 4; j++) {
                float2 ve = up2(acc2[ip*2    ][j]);
                float2 vo = up2(acc2[ip*2 + 1][j]);
                int twa = tx*8 + 2*j;
                float2 csa = Ts[e][twa];
                float2 csb = Ts[e][twa + 1];
                re[2*j]   = ve.x*csa.x - vo.x*csa.y;
                ro[2*j]   = vo.x*csa.x + ve.x*csa.y;
                re[2*j+1] = ve.y*csb.x - vo.y*csb.y;
                ro[2*j+1] = vo.y*csb.x + ve.y*csb.y;
            }
            float* oe = &Out[(size_t)g*WW + w0 + tx*8];
            float* oo = &Out[(size_t)(g+1)*WW + w0 + tx*8];
            *reinterpret_cast<float4*>(oe)     = make_float4(re[0], re[1], re[2], re[3]);
            *reinterpret_cast<float4*>(oe + 4) = make_float4(re[4], re[5], re[6], re[7]);
            *reinterpret_cast<float4*>(oo)     = make_float4(ro[0], ro[1], ro[2], ro[3]);
            *reinterpret_cast<float4*>(oo + 4) = make_float4(ro[4], ro[5], ro[6], ro[7]);
        }
    }
}

// =====================================================================
// K3: flash attention v13 = R11 (best: 277.7us) + kx-specialized PV
//   loop (unroll-time constant swizzled rows -> immediate LDS offsets)
//   + hoisted Ps-store row pointers in the epilogue.
// grid (6, 128), block 256, dyn smem 86528 B (2 CTA/SM).
// =====================================================================
#define FL_SMEM (( 32*132 + 2*32*68 + 2*64*36 + 64*132 ) * 4)

__global__ __launch_bounds__(256, 2)
void flash_kernel(const float* __restrict__ prev_qk, float* __restrict__ qk_out)
{
    extern __shared__ float sm[];
    float* Qs  = sm;                  // [32][132]   [d][q]
    float* Ksb = Qs + 32*132;         // [2][32][68] [d][k]
    float* Vsb = Ksb + 2*32*68;       // [2][64][36] [k][d]
    float* Ps  = Vsb + 2*64*36;       // [64][132]   [k(swz)][q] / O staging

    int q0    = blockIdx.x * 128;
    int batch = blockIdx.y;
    int bmi = batch >> 3, h = batch & 7;
    size_t gbase = ((size_t)bmi*FF + h*32) * WW;
    const float* Qb = g_q + gbase;
    const float* Kb = g_k + gbase;
    const float* Vb = g_v + gbase;

    int tid = threadIdx.x;
    int ty = tid >> 4, tx = tid & 15;
    int dsel = tx & 7, kx = tx >> 3;
    int lr = tid >> 4, lc4 = (tid & 15) * 4;
    int ksw = (tx >> 1) & 7;     // Ps swizzle key for this thread's k block

    // ---- load Q tile: 32 d x 128 q ----
    #pragma unroll
    for (int it = 0; it < 4; it++) {
        int li = tid + it*256;
        int d = li >> 5, c4 = (li & 31) * 4;
        *reinterpret_cast<float4*>(&Qs[d*132 + c4]) =
            *reinterpret_cast<const float4*>(&Qb[(size_t)d*WW + q0 + c4]);
    }

    // ---- load K/V tile 0 directly into buffer 0 ----
    {
        float4 k0v = *reinterpret_cast<const float4*>(&Kb[(size_t)lr*WW + lc4]);
        float4 k1v = *reinterpret_cast<const float4*>(&Kb[(size_t)(lr+16)*WW + lc4]);
        float4 v0v = *reinterpret_cast<const float4*>(&Vb[(size_t)lr*WW + lc4]);
        float4 v1v = *reinterpret_cast<const float4*>(&Vb[(size_t)(lr+16)*WW + lc4]);
        *reinterpret_cast<float4*>(&Ksb[lr*68 + lc4])      = k0v;
        *reinterpret_cast<float4*>(&Ksb[(lr+16)*68 + lc4]) = k1v;
        Vsb[(lc4+0)*36 + lr] = v0v.x; Vsb[(lc4+1)*36 + lr] = v0v.y;
        Vsb[(lc4+2)*36 + lr] = v0v.z; Vsb[(lc4+3)*36 + lr] = v0v.w;
        Vsb[(lc4+0)*36 + lr+16] = v1v.x; Vsb[(lc4+1)*36 + lr+16] = v1v.y;
        Vsb[(lc4+2)*36 + lr+16] = v1v.z; Vsb[(lc4+3)*36 + lr+16] = v1v.w;
    }
    __syncthreads();

    float l_i[8] = {0,0,0,0,0,0,0,0};
    ull o2[4][4];
    #pragma unroll
    for (int i = 0; i < 4; i++)
        #pragma unroll
        for (int j = 0; j < 4; j++) o2[i][j] = 0ull;

    const float scale = 1.f/16.f;
    size_t qkbase = (size_t)batch * WW * WW;

    // hoisted swizzled Ps-store row pointers (qp-invariant)
    float* psrow[4];
    {
        int kb = tx*4;
        psrow[0] = &Ps[((kb+0)^ksw)*132];
        psrow[1] = &Ps[((kb+1)^ksw)*132];
        psrow[2] = &Ps[((kb+2)^ksw)*132];
        psrow[3] = &Ps[((kb+3)^ksw)*132];
    }

    float4 kr0, kr1, vr0, vr1;
    for (int kt = 0; kt < 12; kt++) {
        int k0 = kt * 64;
        int cur = kt & 1, nxt = cur ^ 1;
        const float* Ks = Ksb + cur*32*68;
        const float* Vs = Vsb + cur*64*36;

        // ---- S = Q @ K^T ----
        ull acc2[4][4];
        #pragma unroll
        for (int i = 0; i < 4; i++)
            #pragma unroll
            for (int j = 0; j < 4; j++) acc2[i][j] = 0ull;

        #pragma unroll
        for (int d = 0; d < 32; d++) {
            ulonglong2 qA = *reinterpret_cast<const ulonglong2*>(&Qs[d*132 + ty*8]);
            ulonglong2 qB = *reinterpret_cast<const ulonglong2*>(&Qs[d*132 + ty*8 + 4]);
            float4 kv = *reinterpret_cast<const float4*>(&Ks[d*68 + tx*4]);
            ull k0b = bc2(kv.x), k1b = bc2(kv.y), k2b = bc2(kv.z), k3b = bc2(kv.w);
            fma2(acc2[0][0], qA.x, k0b); fma2(acc2[0][1], qA.x, k1b); fma2(acc2[0][2], qA.x, k2b); fma2(acc2[0][3], qA.x, k3b);
            fma2(acc2[1][0], qA.y, k0b); fma2(acc2[1][1], qA.y, k1b); fma2(acc2[1][2], qA.y, k2b); fma2(acc2[1][3], qA.y, k3b);
            fma2(acc2[2][0], qB.x, k0b); fma2(acc2[2][1], qB.x, k1b); fma2(acc2[2][2], qB.x, k2b); fma2(acc2[2][3], qB.x, k3b);
            fma2(acc2[3][0], qB.y, k0b); fma2(acc2[3][1], qB.y, k1b); fma2(acc2[3][2], qB.y, k2b); fma2(acc2[3][3], qB.y, k3b);
        }

        // ---- prefetch next K/V tile into registers ----
        if (kt < 11) {
            int k1 = k0 + 64;
            kr0 = *reinterpret_cast<const float4*>(&Kb[(size_t)lr*WW + k1 + lc4]);
            kr1 = *reinterpret_cast<const float4*>(&Kb[(size_t)(lr+16)*WW + k1 + lc4]);
            vr0 = *reinterpret_cast<const float4*>(&Vb[(size_t)lr*WW + k1 + lc4]);
            vr1 = *reinterpret_cast<const float4*>(&Vb[(size_t)(lr+16)*WW + k1 + lc4]);
        }

        // ---- epilogue: qk write + max-free softmax + swizzled P store ----
        #pragma unroll
        for (int qp = 0; qp < 4; qp++) {
            float2 s0 = up2(acc2[qp][0]);
            float2 s1 = up2(acc2[qp][1]);
            float2 s2 = up2(acc2[qp][2]);
            float2 s3 = up2(acc2[qp][3]);
            int ra = ty*8 + qp*2;
            size_t rowa = qkbase + (size_t)(q0 + ra)*WW + k0 + tx*4;
            float4 pva = *reinterpret_cast<const float4*>(&prev_qk[rowa]);
            float4 pvb = *reinterpret_cast<const float4*>(&prev_qk[rowa + WW]);
            float sa0 = fmaf(s0.x, scale, pva.x), sa1 = fmaf(s1.x, scale, pva.y);
            float sa2 = fmaf(s2.x, scale, pva.z), sa3 = fmaf(s3.x, scale, pva.w);
            float sb0 = fmaf(s0.y, scale, pvb.x), sb1 = fmaf(s1.y, scale, pvb.y);
            float sb2 = fmaf(s2.y, scale, pvb.z), sb3 = fmaf(s3.y, scale, pvb.w);
            *reinterpret_cast<float4*>(&qk_out[rowa])      = make_float4(sa0,sa1,sa2,sa3);
            *reinterpret_cast<float4*>(&qk_out[rowa + WW]) = make_float4(sb0,sb1,sb2,sb3);
            float pa0 = __expf(sa0), pa1 = __expf(sa1), pa2 = __expf(sa2), pa3 = __expf(sa3);
            float pb0 = __expf(sb0), pb1 = __expf(sb1), pb2 = __expf(sb2), pb3 = __expf(sb3);
            l_i[qp*2  ] += (pa0 + pa1) + (pa2 + pa3);
            l_i[qp*2+1] += (pb0 + pb1) + (pb2 + pb3);
            *reinterpret_cast<ull*>(psrow[0] + ra) = pk2(pa0, pb0);
            *reinterpret_cast<ull*>(psrow[1] + ra) = pk2(pa1, pb1);
            *reinterpret_cast<ull*>(psrow[2] + ra) = pk2(pa2, pb2);
            *reinterpret_cast<ull*>(psrow[3] + ra) = pk2(pa3, pb3);
        }
        __syncthreads();   // [A] Ps ready; QK done with Ks[cur]

        // ---- store next K/V into alternate buffers (PV reads cur only) ----
        if (kt < 11) {
            float* Kn = Ksb + nxt*32*68;
            float* Vn = Vsb + nxt*64*36;
            *reinterpret_cast<float4*>(&Kn[lr*68 + lc4])      = kr0;
            *reinterpret_cast<float4*>(&Kn[(lr+16)*68 + lc4]) = kr1;
            Vn[(lc4+0)*36 + lr] = vr0.x; Vn[(lc4+1)*36 + lr] = vr0.y;
            Vn[(lc4+2)*36 + lr] = vr0.z; Vn[(lc4+3)*36 + lr] = vr0.w;
            Vn[(lc4+0)*36 + lr+16] = vr1.x; Vn[(lc4+1)*36 + lr+16] = vr1.y;
            Vn[(lc4+2)*36 + lr+16] = vr1.z; Vn[(lc4+3)*36 + lr+16] = vr1.w;
        }

        // ---- O += P @ V, kx-specialized (unroll-time constant rows) ----
        #define PV_STEP(kconst) { \
            const int kcc = (kconst); \
            const int rcc = kcc ^ ((kcc >> 3) & 7); \
            ulonglong2 pA = *reinterpret_cast<const ulonglong2*>(&Ps[rcc*132 + ty*8]); \
            ulonglong2 pB = *reinterpret_cast<const ulonglong2*>(&Ps[rcc*132 + ty*8 + 4]); \
            float4 vv = *reinterpret_cast<const float4*>(&Vs[kcc*36 + dsel*4]); \
            ull v0 = bc2(vv.x), v1 = bc2(vv.y), v2 = bc2(vv.z), v3 = bc2(vv.w); \
            fma2(o2[0][0], pA.x, v0); fma2(o2[0][1], pA.x, v1); fma2(o2[0][2], pA.x, v2); fma2(o2[0][3], pA.x, v3); \
            fma2(o2[1][0], pA.y, v0); fma2(o2[1][1], pA.y, v1); fma2(o2[1][2], pA.y, v2); fma2(o2[1][3], pA.y, v3); \
            fma2(o2[2][0], pB.x, v0); fma2(o2[2][1], pB.x, v1); fma2(o2[2][2], pB.x, v2); fma2(o2[2][3], pB.x, v3); \
            fma2(o2[3][0], pB.y, v0); fma2(o2[3][1], pB.y, v1); fma2(o2[3][2], pB.y, v2); fma2(o2[3][3], pB.y, v3); \
        }
        if (kx == 0) {
            #pragma unroll
            for (int kk = 0; kk < 32; kk++) PV_STEP(kk);
        } else {
            #pragma unroll
            for (int kk = 0; kk < 32; kk++) PV_STEP(32 + kk);
        }
        #undef PV_STEP
        __syncthreads();   // [B] PV done with Ps; next buffers visible
    }

    // ---- finalize: reduce k-halves, l; stage; write ----
    #pragma unroll
    for (int i = 0; i < 4; i++)
        #pragma unroll
        for (int j = 0; j < 4; j++) {
            float2 v = up2(o2[i][j]);
            v.x += __shfl_xor_sync(0xffffffffu, v.x, 8);
            v.y += __shfl_xor_sync(0xffffffffu, v.y, 8);
            o2[i][j] = pk2(v.x, v.y);
        }
    #pragma unroll
    for (int r = 0; r < 8; r++) {
        float lv = l_i[r];
        lv += __shfl_xor_sync(0xffffffffu, lv, 1);
        lv += __shfl_xor_sync(0xffffffffu, lv, 2);
        lv += __shfl_xor_sync(0xffffffffu, lv, 4);
        lv += __shfl_xor_sync(0xffffffffu, lv, 8);
        l_i[r] = lv;
    }

    if (kx == 0) {
        float rl[8];
        #pragma unroll
        for (int r = 0; r < 8; r++) rl[r] = 1.0f / l_i[r];
        #pragma unroll
        for (int qp = 0; qp < 4; qp++)
            #pragma unroll
            for (int j = 0; j < 4; j++) {
                float2 v = up2(o2[qp][j]);
                int d = dsel*4 + j;
                int qq = ty*8 + qp*2;
                Ps[d*132 + qq]     = v.x * rl[qp*2];
                Ps[d*132 + qq + 1] = v.y * rl[qp*2+1];
            }
    }
    __syncthreads();

    #pragma unroll
    for (int it = 0; it < 4; it++) {
        int li = tid + it*256;
        int d = li >> 5, c4 = (li & 31) * 4;
        *reinterpret_cast<float4*>(&g_a[((size_t)bmi*FF + h*DHH + d)*WW + q0 + c4]) =
            *reinterpret_cast<const float4*>(&Ps[d*132 + c4]);
    }
}

// =====================================================================
// K5a: o positionwise proj, 128x128 tile, register-prefetched.
// =====================================================================
__global__ __launch_bounds__(256, 2)
void opw_kernel(const float* __restrict__ x, const float* __restrict__ opw)
{
    int z = blockIdx.z;
    int b = z / CA, c = z % CA;
    const float* A  = opw + (size_t)c*FF*FF;
    const float* Bm = (c < CH) ? (x   + (size_t)(b*CH + c     )*FF*WW)
                               : (g_a + (size_t)(b*AM + c - CH)*FF*WW);
    float* Out = g_o1 + (size_t)(b*CA + c)*FF*WW;

    __shared__ float As[16][132];
    __shared__ float Bs[16][132];

    int g0 = blockIdx.x * 128, w0 = blockIdx.y * 128;
    int tid = threadIdx.x;
    int ty = tid >> 4, tx = tid & 15;

    int la_r[2], la_c[2], lb_r[2], lb_c[2];
    #pragma unroll
    for (int it = 0; it < 2; it++) {
        int li = tid + it*256;
        la_r[it] = li >> 2;  la_c[it] = (li & 3) * 4;
        lb_r[it] = li >> 5;  lb_c[it] = (li & 31) * 4;
    }
    float4 ra[2], rb[2];
    #pragma unroll
    for (int it = 0; it < 2; it++) {
        ra[it] = *reinterpret_cast<const float4*>(&A[(size_t)(g0 + la_r[it])*FF + la_c[it]]);
        rb[it] = *reinterpret_cast<const float4*>(&Bm[(size_t)lb_r[it]*WW + w0 + lb_c[it]]);
    }

    ull acc2[8][4];
    #pragma unroll
    for (int i = 0; i < 8; i++)
        #pragma unroll
        for (int j = 0; j < 4; j++) acc2[i][j] = 0ull;

    for (int f0 = 0; f0 < FF; f0 += 16) {
        if (f0) __syncthreads();
        #pragma unroll
        for (int it = 0; it < 2; it++) {
            As[la_c[it]+0][la_r[it]] = ra[it].x;
            As[la_c[it]+1][la_r[it]] = ra[it].y;
            As[la_c[it]+2][la_r[it]] = ra[it].z;
            As[la_c[it]+3][la_r[it]] = ra[it].w;
            *reinterpret_cast<float4*>(&Bs[lb_r[it]][lb_c[it]]) = rb[it];
        }
        __syncthreads();
        if (f0 + 16 < FF) {
            int f1 = f0 + 16;
            #pragma unroll
            for (int it = 0; it < 2; it++) {
                ra[it] = *reinterpret_cast<const float4*>(&A[(size_t)(g0 + la_r[it])*FF + f1 + la_c[it]]);
                rb[it] = *reinterpret_cast<const float4*>(&Bm[(size_t)(f1 + lb_r[it])*WW + w0 + lb_c[it]]);
            }
        }

        #pragma unroll
        for (int kk = 0; kk < 16; kk++) {
            float4 a0 = *reinterpret_cast<const float4*>(&As[kk][ty*8]);
            float4 a1 = *reinterpret_cast<const float4*>(&As[kk][ty*8 + 4]);
            ulonglong2 b0 = *reinterpret_cast<const ulonglong2*>(&Bs[kk][tx*8]);
            ulonglong2 b1 = *reinterpret_cast<const ulonglong2*>(&Bs[kk][tx*8 + 4]);
            ull av0 = bc2(a0.x), av1 = bc2(a0.y), av2 = bc2(a0.z), av3 = bc2(a0.w);
            ull av4 = bc2(a1.x), av5 = bc2(a1.y), av6 = bc2(a1.z), av7 = bc2(a1.w);
            fma2(acc2[0][0], av0, b0.x); fma2(acc2[0][1], av0, b0.y); fma2(acc2[0][2], av0, b1.x); fma2(acc2[0][3], av0, b1.y);
            fma2(acc2[1][0], av1, b0.x); fma2(acc2[1][1], av1, b0.y); fma2(acc2[1][2], av1, b1.x); fma2(acc2[1][3], av1, b1.y);
            fma2(acc2[2][0], av2, b0.x); fma2(acc2[2][1], av2, b0.y); fma2(acc2[2][2], av2, b1.x); fma2(acc2[2][3], av2, b1.y);
            fma2(acc2[3][0], av3, b0.x); fma2(acc2[3][1], av3, b0.y); fma2(acc2[3][2], av3, b1.x); fma2(acc2[3][3], av3, b1.y);
            fma2(acc2[4][0], av4, b0.x); fma2(acc2[4][1], av4, b0.y); fma2(acc2[4][2], av4, b1.x); fma2(acc2[4][3], av4, b1.y);
            fma2(acc2[5][0], av5, b0.x); fma2(acc2[5][1], av5, b0.y); fma2(acc2[5][2], av5, b1.x); fma2(acc2[5][3], av5, b1.y);
            fma2(acc2[6][0], av6, b0.x); fma2(acc2[6][1], av6, b0.y); fma2(acc2[6][2], av6, b1.x); fma2(acc2[6][3], av6, b1.y);
            fma2(acc2[7][0], av7, b0.x); fma2(acc2[7][1], av7, b0.y); fma2(acc2[7][2], av7, b1.x); fma2(acc2[7][3], av7, b1.y);
        }
    }

    #pragma unroll
    for (int i = 0; i < 8; i++) {
        int g = g0 + ty*8 + i;
        float r_[8];
        #pragma unroll
        for (int j = 0; j < 4; j++) {
            float2 f2 = up2(acc2[i][j]);
            r_[2*j] = f2.x; r_[2*j+1] = f2.y;
        }
        float* op = &Out[(size_t)g*WW + w0 + tx*8];
        *reinterpret_cast<float4*>(op)     = make_float4(r_[0], r_[1], r_[2], r_[3]);
        *reinterpret_cast<float4*>(op + 4) = make_float4(r_[4], r_[5], r_[6], r_[7]);
    }
}

// =====================================================================
// K5b: depthwise channel mix (float4)
// =====================================================================
__global__ __launch_bounds__(256)
void mix_kernel(const float* __restrict__ o_dw, float* __restrict__ out)
{
    int idx = blockIdx.x * 256 + threadIdx.x;
    int b   = idx / (FF*WW/4);
    int gw4 = idx % (FF*WW/4);

    __shared__ float sdw[CH*CA];
    if (threadIdx.x < CH*CA) sdw[threadIdx.x] = o_dw[threadIdx.x];
    __syncthreads();

    float4 vc[CA];
    #pragma unroll
    for (int c = 0; c < CA; c++)
        vc[c] = *reinterpret_cast<const float4*>(&g_o1[(size_t)(b*CA + c)*FF*WW + gw4*4]);

    #pragma unroll
    for (int d = 0; d < CH; d++) {
        float4 s = make_float4(0.f, 0.f, 0.f, 0.f);
        #pragma unroll
        for (int c = 0; c < CA; c++) {
            float wdc = sdw[d*CA + c];
            s.x = fmaf(wdc, vc[c].x, s.x);
            s.y = fmaf(wdc, vc[c].y, s.y);
            s.z = fmaf(wdc, vc[c].z, s.z);
            s.w = fmaf(wdc, vc[c].w, s.w);
        }
        *reinterpret_cast<float4*>(&out[(size_t)(b*CH + d)*FF*WW + gw4*4]) = s;
    }
}

// =====================================================================
extern "C" void kernel_launch(void* const* d_in, const int* in_sizes, int n_in,
                              void* d_out, int out_size)
{
    const float* x       = (const float*)d_in[0];
    const float* prev_qk = (const float*)d_in[1];
    const float* q_pw = (const float*)d_in[4];
    const float* k_pw = (const float*)d_in[7];
    const float* v_pw = (const float*)d_in[10];
    const float* o_pw = (const float*)d_in[11];
    const float* o_dw = (const float*)d_in[12];

    cudaMemcpyToSymbolAsync(c_qcw, d_in[2], AM*CH*9*sizeof(float), 0, cudaMemcpyDeviceToDevice);
    cudaMemcpyToSymbolAsync(c_qcb, d_in[3], AM*sizeof(float),      0, cudaMemcpyDeviceToDevice);
    cudaMemcpyToSymbolAsync(c_kcw, d_in[5], AM*CH*9*sizeof(float), 0, cudaMemcpyDeviceToDevice);
    cudaMemcpyToSymbolAsync(c_kcb, d_in[6], AM*sizeof(float),      0, cudaMemcpyDeviceToDevice);
    cudaMemcpyToSymbolAsync(c_vcw, d_in[8], AM*CH*9*sizeof(float), 0, cudaMemcpyDeviceToDevice);
    cudaMemcpyToSymbolAsync(c_vcb, d_in[9], AM*sizeof(float),      0, cudaMemcpyDeviceToDevice);

    static bool attr_set = false;
    if (!attr_set) {
        cudaFuncSetAttribute(flash_kernel, cudaFuncAttributeMaxDynamicSharedMemorySize, FL_SMEM);
        attr_set = true;
    }

    float* out_main = (float*)d_out;                  // (B,CH,F,W)
    float* qk_out   = (float*)d_out + OUT_ELEMS;      // (B,AM,NH,W,W)

    cs_init_kernel<<<dim3((16*WW + 255)/256), 256>>>();
    conv_kernel<<<dim3(FF, BB*AM), 384>>>(x);
    pw_kernel<<<dim3(FF/128, WW/128, 3*BB*AM), 256>>>(q_pw, k_pw, v_pw);
    flash_kernel<<<dim3(WW/128, BB*AM*NHH), 256, FL_SMEM>>>(prev_qk, qk_out);
    opw_kernel<<<dim3(FF/128, WW/128, BB*CA), 256>>>(x, o_pw);
    mix_kernel<<<dim3(BB*FF*WW/1024), 256>>>(o_dw, out_main);
}

// round 15
// speedup vs baseline: 1.1498x; 1.1498x over previous
#include <cuda_runtime.h>

#define BB  2
#define CH  8
#define AM  8
#define NHH 8
#define FF  256
#define WW  768
#define DHH 32
#define CA  16   // CH + AM

#define YSZ (BB*AM*FF*WW)         // 3,145,728
#define OUT_ELEMS (BB*CH*FF*WW)   // 3,145,728

typedef unsigned long long ull;

// ---- scratch (static device memory; allocation is forbidden) ----
__device__ float g_yq[YSZ];
__device__ float g_yk[YSZ];
__device__ float g_yv[YSZ];
__device__ float g_q [YSZ];   // (b,m, g=h*32+d, w)
__device__ float g_k [YSZ];
__device__ float g_v [YSZ];
__device__ float g_a [YSZ];   // attention result (b,m,f,w)
__device__ float g_o1[BB*CA*FF*WW];
__device__ float2 g_cs[16*WW];  // RoPE table: [e][w] -> (cos, sin)

// conv weights in constant memory
__constant__ float c_qcw[AM*CH*9];
__constant__ float c_kcw[AM*CH*9];
__constant__ float c_vcw[AM*CH*9];
__constant__ float c_qcb[AM];
__constant__ float c_kcb[AM];
__constant__ float c_vcb[AM];

// ---------- packed f32x2 helpers ----------
__device__ __forceinline__ ull bc2(float v) {
    ull r; asm("mov.b64 %0, {%1, %1};" : "=l"(r) : "f"(v)); return r;
}
__device__ __forceinline__ ull pk2(float lo, float hi) {
    ull r; asm("mov.b64 %0, {%1, %2};" : "=l"(r) : "f"(lo), "f"(hi)); return r;
}
__device__ __forceinline__ void fma2(ull& d, ull a, ull b) {
    asm("fma.rn.f32x2 %0, %1, %2, %0;" : "+l"(d) : "l"(a), "l"(b));
}
__device__ __forceinline__ float2 up2(ull v) {
    float lo, hi; asm("mov.b64 {%0, %1}, %2;" : "=f"(lo), "=f"(hi) : "l"(v));
    return make_float2(lo, hi);
}

// =====================================================================
// K0: RoPE cos/sin table init
// =====================================================================
__global__ void cs_init_kernel()
{
    int idx = blockIdx.x * 256 + threadIdx.x;
    if (idx >= 16*WW) return;
    int e = idx / WW, w = idx % WW;
    float inv = expf(-(float)(2*e) * (9.210340371976184f / 32.0f));
    float s, c;
    sincosf((float)w * inv, &s, &c);
    g_cs[idx] = make_float2(c, s);
}

// =====================================================================
// K1: 3x3 conv + bias for q,k,v. 2 outputs/thread via f32x2.
// =====================================================================
__global__ __launch_bounds__(384)
void conv_kernel(const float* __restrict__ x)
{
    int tid = threadIdx.x;
    int w0  = tid * 2;
    int f   = blockIdx.x;
    int bm  = blockIdx.y;
    int m = bm % AM, b = bm / AM;

    ull aq = bc2(c_qcb[m]), ak = bc2(c_kcb[m]), av = bc2(c_vcb[m]);

    #pragma unroll
    for (int ci = 0; ci < CH; ci++) {
        const float* xp = x + (size_t)((b*CH + ci)*FF) * WW;
        #pragma unroll
        for (int kh = 0; kh < 3; kh++) {
            int ff = f + kh - 1;
            if (ff < 0 || ff >= FF) continue;
            const float* xr = xp + ff*WW;
            float xm1 = (w0 > 0)      ? xr[w0-1] : 0.f;
            float2 xc = *reinterpret_cast<const float2*>(&xr[w0]);
            float x2  = (w0+2 < WW)   ? xr[w0+2] : 0.f;
            ull pm = pk2(xm1, xc.x);
            ull p0 = pk2(xc.x, xc.y);
            ull pp = pk2(xc.y, x2);
            int wb = m*72 + ci*9 + kh*3;
            fma2(aq, pm, bc2(c_qcw[wb+0])); fma2(aq, p0, bc2(c_qcw[wb+1])); fma2(aq, pp, bc2(c_qcw[wb+2]));
            fma2(ak, pm, bc2(c_kcw[wb+0])); fma2(ak, p0, bc2(c_kcw[wb+1])); fma2(ak, pp, bc2(c_kcw[wb+2]));
            fma2(av, pm, bc2(c_vcw[wb+0])); fma2(av, p0, bc2(c_vcw[wb+1])); fma2(av, pp, bc2(c_vcw[wb+2]));
        }
    }
    int oid = ((b*AM + m)*FF + f)*WW + w0;
    float2 q2 = up2(aq), k2 = up2(ak), v2 = up2(av);
    *reinterpret_cast<float2*>(&g_yq[oid]) = q2;
    *reinterpret_cast<float2*>(&g_yk[oid]) = k2;
    *reinterpret_cast<float2*>(&g_yv[oid]) = v2;
}

// =====================================================================
// K2: positionwise linear, 128x128 tile, 8x8 microtile, f32x2,
// register-prefetched k-slices.
// =====================================================================
__global__ __launch_bounds__(256, 2)
void pw_kernel(const float* __restrict__ qpw,
               const float* __restrict__ kpw,
               const float* __restrict__ vpw)
{
    int z  = blockIdx.z;
    int p  = z / (BB*AM);     // 0=q 1=k 2=v
    int bm = z % (BB*AM);
    int m  = bm % AM;

    const float* A  = (p == 0 ? qpw : (p == 1 ? kpw : vpw)) + (size_t)m*FF*FF;      // (g,f)
    const float* Bm = (p == 0 ? g_yq : (p == 1 ? g_yk : g_yv)) + (size_t)bm*FF*WW;  // (f,w)
    float*      Out = (p == 0 ? g_q : (p == 1 ? g_k : g_v)) + (size_t)bm*FF*WW;     // (g,w)

    __shared__ float  As[16][132];   // [f][g]
    __shared__ float  Bs[16][132];   // [f][w]
    __shared__ float2 Ts[16][128];   // [e][w-local]

    int g0 = blockIdx.x * 128, w0 = blockIdx.y * 128;
    int tid = threadIdx.x;
    int ty = tid >> 4, tx = tid & 15;

    if (p < 2) {
        #pragma unroll
        for (int it = 0; it < 8; it++) {
            int li = tid + it*256;
            int e = li >> 7, tw = li & 127;
            Ts[e][tw] = g_cs[e*WW + w0 + tw];
        }
    }

    int la_r[2], la_c[2], lb_r[2], lb_c[2];
    #pragma unroll
    for (int it = 0; it < 2; it++) {
        int li = tid + it*256;
        la_r[it] = li >> 2;  la_c[it] = (li & 3) * 4;
        lb_r[it] = li >> 5;  lb_c[it] = (li & 31) * 4;
    }

    float4 ra[2], rb[2];
    #pragma unroll
    for (int it = 0; it < 2; it++) {
        ra[it] = *reinterpret_cast<const float4*>(&A[(size_t)(g0 + la_r[it])*FF + la_c[it]]);
        rb[it] = *reinterpret_cast<const float4*>(&Bm[(size_t)lb_r[it]*WW + w0 + lb_c[it]]);
    }

    ull acc2[8][4];
    #pragma unroll
    for (int i = 0; i < 8; i++)
        #pragma unroll
        for (int j = 0; j < 4; j++) acc2[i][j] = 0ull;

    for (int f0 = 0; f0 < FF; f0 += 16) {
        if (f0) __syncthreads();
        #pragma unroll
        for (int it = 0; it < 2; it++) {
            As[la_c[it]+0][la_r[it]] = ra[it].x;
            As[la_c[it]+1][la_r[it]] = ra[it].y;
            As[la_c[it]+2][la_r[it]] = ra[it].z;
            As[la_c[it]+3][la_r[it]] = ra[it].w;
            *reinterpret_cast<float4*>(&Bs[lb_r[it]][lb_c[it]]) = rb[it];
        }
        __syncthreads();
        if (f0 + 16 < FF) {
            int f1 = f0 + 16;
            #pragma unroll
            for (int it = 0; it < 2; it++) {
                ra[it] = *reinterpret_cast<const float4*>(&A[(size_t)(g0 + la_r[it])*FF + f1 + la_c[it]]);
                rb[it] = *reinterpret_cast<const float4*>(&Bm[(size_t)(f1 + lb_r[it])*WW + w0 + lb_c[it]]);
            }
        }

        #pragma unroll
        for (int kk = 0; kk < 16; kk++) {
            float4 a0 = *reinterpret_cast<const float4*>(&As[kk][ty*8]);
            float4 a1 = *reinterpret_cast<const float4*>(&As[kk][ty*8 + 4]);
            ulonglong2 b0 = *reinterpret_cast<const ulonglong2*>(&Bs[kk][tx*8]);
            ulonglong2 b1 = *reinterpret_cast<const ulonglong2*>(&Bs[kk][tx*8 + 4]);
            ull av0 = bc2(a0.x), av1 = bc2(a0.y), av2 = bc2(a0.z), av3 = bc2(a0.w);
            ull av4 = bc2(a1.x), av5 = bc2(a1.y), av6 = bc2(a1.z), av7 = bc2(a1.w);
            fma2(acc2[0][0], av0, b0.x); fma2(acc2[0][1], av0, b0.y); fma2(acc2[0][2], av0, b1.x); fma2(acc2[0][3], av0, b1.y);
            fma2(acc2[1][0], av1, b0.x); fma2(acc2[1][1], av1, b0.y); fma2(acc2[1][2], av1, b1.x); fma2(acc2[1][3], av1, b1.y);
            fma2(acc2[2][0], av2, b0.x); fma2(acc2[2][1], av2, b0.y); fma2(acc2[2][2], av2, b1.x); fma2(acc2[2][3], av2, b1.y);
            fma2(acc2[3][0], av3, b0.x); fma2(acc2[3][1], av3, b0.y); fma2(acc2[3][2], av3, b1.x); fma2(acc2[3][3], av3, b1.y);
            fma2(acc2[4][0], av4, b0.x); fma2(acc2[4][1], av4, b0.y); fma2(acc2[4][2], av4, b1.x); fma2(acc2[4][3], av4, b1.y);
            fma2(acc2[5][0], av5, b0.x); fma2(acc2[5][1], av5, b0.y); fma2(acc2[5][2], av5, b1.x); fma2(acc2[5][3], av5, b1.y);
            fma2(acc2[6][0], av6, b0.x); fma2(acc2[6][1], av6, b0.y); fma2(acc2[6][2], av6, b1.x); fma2(acc2[6][3], av6, b1.y);
            fma2(acc2[7][0], av7, b0.x); fma2(acc2[7][1], av7, b0.y); fma2(acc2[7][2], av7, b1.x); fma2(acc2[7][3], av7, b1.y);
        }
    }

    if (p == 2) {
        #pragma unroll
        for (int i = 0; i < 8; i++) {
            int g = g0 + ty*8 + i;
            float r_[8];
            #pragma unroll
            for (int j = 0; j < 4; j++) {
                float2 f2 = up2(acc2[i][j]);
                r_[2*j] = f2.x; r_[2*j+1] = f2.y;
            }
            float* op = &Out[(size_t)g*WW + w0 + tx*8];
            *reinterpret_cast<float4*>(op)     = make_float4(r_[0], r_[1], r_[2], r_[3]);
            *reinterpret_cast<float4*>(op + 4) = make_float4(r_[4], r_[5], r_[6], r_[7]);
        }
    } else {
        #pragma unroll
        for (int ip = 0; ip < 4; ip++) {
            int g = g0 + ty*8 + ip*2;
            int e = (g & 31) >> 1;
            float re[8], ro[8];
            #pragma unroll
            for (int j = 0; j < 4; j++) {
                float2 ve = up2(acc2[ip*2    ][j]);
                float2 vo = up2(acc2[ip*2 + 1][j]);
                int twa = tx*8 + 2*j;
                float2 csa = Ts[e][twa];
                float2 csb = Ts[e][twa + 1];
                re[2*j]   = ve.x*csa.x - vo.x*csa.y;
                ro[2*j]   = vo.x*csa.x + ve.x*csa.y;
                re[2*j+1] = ve.y*csb.x - vo.y*csb.y;
                ro[2*j+1] = vo.y*csb.x + ve.y*csb.y;
            }
            float* oe = &Out[(size_t)g*WW + w0 + tx*8];
            float* oo = &Out[(size_t)(g+1)*WW + w0 + tx*8];
            *reinterpret_cast<float4*>(oe)     = make_float4(re[0], re[1], re[2], re[3]);
            *reinterpret_cast<float4*>(oe + 4) = make_float4(re[4], re[5], re[6], re[7]);
            *reinterpret_cast<float4*>(oo)     = make_float4(ro[0], ro[1], ro[2], ro[3]);
            *reinterpret_cast<float4*>(oo + 4) = make_float4(ro[4], ro[5], ro[6], ro[7]);
        }
    }
}

// =====================================================================
// K3: flash attention v15 = R11 champion (277.7us) with uniform PV loop
//   (NO kx branch — it diverges intra-warp) + hoisted Ps-store pointers.
// grid (6, 128), block 256, dyn smem 86528 B (2 CTA/SM).
// =====================================================================
#define FL_SMEM (( 32*132 + 2*32*68 + 2*64*36 + 64*132 ) * 4)

__global__ __launch_bounds__(256, 2)
void flash_kernel(const float* __restrict__ prev_qk, float* __restrict__ qk_out)
{
    extern __shared__ float sm[];
    float* Qs  = sm;                  // [32][132]   [d][q]
    float* Ksb = Qs + 32*132;         // [2][32][68] [d][k]
    float* Vsb = Ksb + 2*32*68;       // [2][64][36] [k][d]
    float* Ps  = Vsb + 2*64*36;       // [64][132]   [k(swz)][q] / O staging

    int q0    = blockIdx.x * 128;
    int batch = blockIdx.y;
    int bmi = batch >> 3, h = batch & 7;
    size_t gbase = ((size_t)bmi*FF + h*32) * WW;
    const float* Qb = g_q + gbase;
    const float* Kb = g_k + gbase;
    const float* Vb = g_v + gbase;

    int tid = threadIdx.x;
    int ty = tid >> 4, tx = tid & 15;
    int dsel = tx & 7, kx = tx >> 3;
    int lr = tid >> 4, lc4 = (tid & 15) * 4;
    int ksw = (tx >> 1) & 7;     // Ps swizzle key for this thread's k block

    // ---- load Q tile: 32 d x 128 q ----
    #pragma unroll
    for (int it = 0; it < 4; it++) {
        int li = tid + it*256;
        int d = li >> 5, c4 = (li & 31) * 4;
        *reinterpret_cast<float4*>(&Qs[d*132 + c4]) =
            *reinterpret_cast<const float4*>(&Qb[(size_t)d*WW + q0 + c4]);
    }

    // ---- load K/V tile 0 directly into buffer 0 ----
    {
        float4 k0v = *reinterpret_cast<const float4*>(&Kb[(size_t)lr*WW + lc4]);
        float4 k1v = *reinterpret_cast<const float4*>(&Kb[(size_t)(lr+16)*WW + lc4]);
        float4 v0v = *reinterpret_cast<const float4*>(&Vb[(size_t)lr*WW + lc4]);
        float4 v1v = *reinterpret_cast<const float4*>(&Vb[(size_t)(lr+16)*WW + lc4]);
        *reinterpret_cast<float4*>(&Ksb[lr*68 + lc4])      = k0v;
        *reinterpret_cast<float4*>(&Ksb[(lr+16)*68 + lc4]) = k1v;
        Vsb[(lc4+0)*36 + lr] = v0v.x; Vsb[(lc4+1)*36 + lr] = v0v.y;
        Vsb[(lc4+2)*36 + lr] = v0v.z; Vsb[(lc4+3)*36 + lr] = v0v.w;
        Vsb[(lc4+0)*36 + lr+16] = v1v.x; Vsb[(lc4+1)*36 + lr+16] = v1v.y;
        Vsb[(lc4+2)*36 + lr+16] = v1v.z; Vsb[(lc4+3)*36 + lr+16] = v1v.w;
    }
    __syncthreads();

    float l_i[8] = {0,0,0,0,0,0,0,0};
    ull o2[4][4];
    #pragma unroll
    for (int i = 0; i < 4; i++)
        #pragma unroll
        for (int j = 0; j < 4; j++) o2[i][j] = 0ull;

    const float scale = 1.f/16.f;
    size_t qkbase = (size_t)batch * WW * WW;

    // hoisted swizzled Ps-store row pointers (qp-invariant)
    float* psrow0; float* psrow1; float* psrow2; float* psrow3;
    {
        int kb = tx*4;
        psrow0 = &Ps[((kb+0)^ksw)*132];
        psrow1 = &Ps[((kb+1)^ksw)*132];
        psrow2 = &Ps[((kb+2)^ksw)*132];
        psrow3 = &Ps[((kb+3)^ksw)*132];
    }

    float4 kr0, kr1, vr0, vr1;
    for (int kt = 0; kt < 12; kt++) {
        int k0 = kt * 64;
        int cur = kt & 1, nxt = cur ^ 1;
        const float* Ks = Ksb + cur*32*68;
        const float* Vs = Vsb + cur*64*36;

        // ---- S = Q @ K^T ----
        ull acc2[4][4];
        #pragma unroll
        for (int i = 0; i < 4; i++)
            #pragma unroll
            for (int j = 0; j < 4; j++) acc2[i][j] = 0ull;

        #pragma unroll
        for (int d = 0; d < 32; d++) {
            ulonglong2 qA = *reinterpret_cast<const ulonglong2*>(&Qs[d*132 + ty*8]);
            ulonglong2 qB = *reinterpret_cast<const ulonglong2*>(&Qs[d*132 + ty*8 + 4]);
            float4 kv = *reinterpret_cast<const float4*>(&Ks[d*68 + tx*4]);
            ull k0b = bc2(kv.x), k1b = bc2(kv.y), k2b = bc2(kv.z), k3b = bc2(kv.w);
            fma2(acc2[0][0], qA.x, k0b); fma2(acc2[0][1], qA.x, k1b); fma2(acc2[0][2], qA.x, k2b); fma2(acc2[0][3], qA.x, k3b);
            fma2(acc2[1][0], qA.y, k0b); fma2(acc2[1][1], qA.y, k1b); fma2(acc2[1][2], qA.y, k2b); fma2(acc2[1][3], qA.y, k3b);
            fma2(acc2[2][0], qB.x, k0b); fma2(acc2[2][1], qB.x, k1b); fma2(acc2[2][2], qB.x, k2b); fma2(acc2[2][3], qB.x, k3b);
            fma2(acc2[3][0], qB.y, k0b); fma2(acc2[3][1], qB.y, k1b); fma2(acc2[3][2], qB.y, k2b); fma2(acc2[3][3], qB.y, k3b);
        }

        // ---- prefetch next K/V tile into registers ----
        if (kt < 11) {
            int k1 = k0 + 64;
            kr0 = *reinterpret_cast<const float4*>(&Kb[(size_t)lr*WW + k1 + lc4]);
            kr1 = *reinterpret_cast<const float4*>(&Kb[(size_t)(lr+16)*WW + k1 + lc4]);
            vr0 = *reinterpret_cast<const float4*>(&Vb[(size_t)lr*WW + k1 + lc4]);
            vr1 = *reinterpret_cast<const float4*>(&Vb[(size_t)(lr+16)*WW + k1 + lc4]);
        }

        // ---- epilogue: qk write + max-free softmax + swizzled P store ----
        #pragma unroll
        for (int qp = 0; qp < 4; qp++) {
            float2 s0 = up2(acc2[qp][0]);
            float2 s1 = up2(acc2[qp][1]);
            float2 s2 = up2(acc2[qp][2]);
            float2 s3 = up2(acc2[qp][3]);
            int ra = ty*8 + qp*2;
            size_t rowa = qkbase + (size_t)(q0 + ra)*WW + k0 + tx*4;
            float4 pva = *reinterpret_cast<const float4*>(&prev_qk[rowa]);
            float4 pvb = *reinterpret_cast<const float4*>(&prev_qk[rowa + WW]);
            float sa0 = fmaf(s0.x, scale, pva.x), sa1 = fmaf(s1.x, scale, pva.y);
            float sa2 = fmaf(s2.x, scale, pva.z), sa3 = fmaf(s3.x, scale, pva.w);
            float sb0 = fmaf(s0.y, scale, pvb.x), sb1 = fmaf(s1.y, scale, pvb.y);
            float sb2 = fmaf(s2.y, scale, pvb.z), sb3 = fmaf(s3.y, scale, pvb.w);
            *reinterpret_cast<float4*>(&qk_out[rowa])      = make_float4(sa0,sa1,sa2,sa3);
            *reinterpret_cast<float4*>(&qk_out[rowa + WW]) = make_float4(sb0,sb1,sb2,sb3);
            float pa0 = __expf(sa0), pa1 = __expf(sa1), pa2 = __expf(sa2), pa3 = __expf(sa3);
            float pb0 = __expf(sb0), pb1 = __expf(sb1), pb2 = __expf(sb2), pb3 = __expf(sb3);
            l_i[qp*2  ] += (pa0 + pa1) + (pa2 + pa3);
            l_i[qp*2+1] += (pb0 + pb1) + (pb2 + pb3);
            *reinterpret_cast<ull*>(psrow0 + ra) = pk2(pa0, pb0);
            *reinterpret_cast<ull*>(psrow1 + ra) = pk2(pa1, pb1);
            *reinterpret_cast<ull*>(psrow2 + ra) = pk2(pa2, pb2);
            *reinterpret_cast<ull*>(psrow3 + ra) = pk2(pa3, pb3);
        }
        __syncthreads();   // [A] Ps ready; QK done with Ks[cur]

        // ---- store next K/V into alternate buffers (PV reads cur only) ----
        if (kt < 11) {
            float* Kn = Ksb + nxt*32*68;
            float* Vn = Vsb + nxt*64*36;
            *reinterpret_cast<float4*>(&Kn[lr*68 + lc4])      = kr0;
            *reinterpret_cast<float4*>(&Kn[(lr+16)*68 + lc4]) = kr1;
            Vn[(lc4+0)*36 + lr] = vr0.x; Vn[(lc4+1)*36 + lr] = vr0.y;
            Vn[(lc4+2)*36 + lr] = vr0.z; Vn[(lc4+3)*36 + lr] = vr0.w;
            Vn[(lc4+0)*36 + lr+16] = vr1.x; Vn[(lc4+1)*36 + lr+16] = vr1.y;
            Vn[(lc4+2)*36 + lr+16] = vr1.z; Vn[(lc4+3)*36 + lr+16] = vr1.w;
        }

        // ---- O += P @ V (uniform loop; swizzle-aware rows, broadcast reads) ----
        #pragma unroll
        for (int kk = 0; kk < 32; kk++) {
            int k = kx*32 + kk;
            int r = k ^ ((k >> 3) & 7);
            ulonglong2 pA = *reinterpret_cast<const ulonglong2*>(&Ps[r*132 + ty*8]);
            ulonglong2 pB = *reinterpret_cast<const ulonglong2*>(&Ps[r*132 + ty*8 + 4]);
            float4 vv = *reinterpret_cast<const float4*>(&Vs[k*36 + dsel*4]);
            ull v0 = bc2(vv.x), v1 = bc2(vv.y), v2 = bc2(vv.z), v3 = bc2(vv.w);
            fma2(o2[0][0], pA.x, v0); fma2(o2[0][1], pA.x, v1); fma2(o2[0][2], pA.x, v2); fma2(o2[0][3], pA.x, v3);
            fma2(o2[1][0], pA.y, v0); fma2(o2[1][1], pA.y, v1); fma2(o2[1][2], pA.y, v2); fma2(o2[1][3], pA.y, v3);
            fma2(o2[2][0], pB.x, v0); fma2(o2[2][1], pB.x, v1); fma2(o2[2][2], pB.x, v2); fma2(o2[2][3], pB.x, v3);
            fma2(o2[3][0], pB.y, v0); fma2(o2[3][1], pB.y, v1); fma2(o2[3][2], pB.y, v2); fma2(o2[3][3], pB.y, v3);
        }
        __syncthreads();   // [B] PV done with Ps; next buffers visible
    }

    // ---- finalize: reduce k-halves, l; stage; write ----
    #pragma unroll
    for (int i = 0; i < 4; i++)
        #pragma unroll
        for (int j = 0; j < 4; j++) {
            float2 v = up2(o2[i][j]);
            v.x += __shfl_xor_sync(0xffffffffu, v.x, 8);
            v.y += __shfl_xor_sync(0xffffffffu, v.y, 8);
            o2[i][j] = pk2(v.x, v.y);
        }
    #pragma unroll
    for (int r = 0; r < 8; r++) {
        float lv = l_i[r];
        lv += __shfl_xor_sync(0xffffffffu, lv, 1);
        lv += __shfl_xor_sync(0xffffffffu, lv, 2);
        lv += __shfl_xor_sync(0xffffffffu, lv, 4);
        lv += __shfl_xor_sync(0xffffffffu, lv, 8);
        l_i[r] = lv;
    }

    if (kx == 0) {
        float rl[8];
        #pragma unroll
        for (int r = 0; r < 8; r++) rl[r] = 1.0f / l_i[r];
        #pragma unroll
        for (int qp = 0; qp < 4; qp++)
            #pragma unroll
            for (int j = 0; j < 4; j++) {
                float2 v = up2(o2[qp][j]);
                int d = dsel*4 + j;
                int qq = ty*8 + qp*2;
                Ps[d*132 + qq]     = v.x * rl[qp*2];
                Ps[d*132 + qq + 1] = v.y * rl[qp*2+1];
            }
    }
    __syncthreads();

    #pragma unroll
    for (int it = 0; it < 4; it++) {
        int li = tid + it*256;
        int d = li >> 5, c4 = (li & 31) * 4;
        *reinterpret_cast<float4*>(&g_a[((size_t)bmi*FF + h*DHH + d)*WW + q0 + c4]) =
            *reinterpret_cast<const float4*>(&Ps[d*132 + c4]);
    }
}

// =====================================================================
// K5a: o positionwise proj, 128x128 tile, register-prefetched.
// =====================================================================
__global__ __launch_bounds__(256, 2)
void opw_kernel(const float* __restrict__ x, const float* __restrict__ opw)
{
    int z = blockIdx.z;
    int b = z / CA, c = z % CA;
    const float* A  = opw + (size_t)c*FF*FF;
    const float* Bm = (c < CH) ? (x   + (size_t)(b*CH + c     )*FF*WW)
                               : (g_a + (size_t)(b*AM + c - CH)*FF*WW);
    float* Out = g_o1 + (size_t)(b*CA + c)*FF*WW;

    __shared__ float As[16][132];
    __shared__ float Bs[16][132];

    int g0 = blockIdx.x * 128, w0 = blockIdx.y * 128;
    int tid = threadIdx.x;
    int ty = tid >> 4, tx = tid & 15;

    int la_r[2], la_c[2], lb_r[2], lb_c[2];
    #pragma unroll
    for (int it = 0; it < 2; it++) {
        int li = tid + it*256;
        la_r[it] = li >> 2;  la_c[it] = (li & 3) * 4;
        lb_r[it] = li >> 5;  lb_c[it] = (li & 31) * 4;
    }
    float4 ra[2], rb[2];
    #pragma unroll
    for (int it = 0; it < 2; it++) {
        ra[it] = *reinterpret_cast<const float4*>(&A[(size_t)(g0 + la_r[it])*FF + la_c[it]]);
        rb[it] = *reinterpret_cast<const float4*>(&Bm[(size_t)lb_r[it]*WW + w0 + lb_c[it]]);
    }

    ull acc2[8][4];
    #pragma unroll
    for (int i = 0; i < 8; i++)
        #pragma unroll
        for (int j = 0; j < 4; j++) acc2[i][j] = 0ull;

    for (int f0 = 0; f0 < FF; f0 += 16) {
        if (f0) __syncthreads();
        #pragma unroll
        for (int it = 0; it < 2; it++) {
            As[la_c[it]+0][la_r[it]] = ra[it].x;
            As[la_c[it]+1][la_r[it]] = ra[it].y;
            As[la_c[it]+2][la_r[it]] = ra[it].z;
            As[la_c[it]+3][la_r[it]] = ra[it].w;
            *reinterpret_cast<float4*>(&Bs[lb_r[it]][lb_c[it]]) = rb[it];
        }
        __syncthreads();
        if (f0 + 16 < FF) {
            int f1 = f0 + 16;
            #pragma unroll
            for (int it = 0; it < 2; it++) {
                ra[it] = *reinterpret_cast<const float4*>(&A[(size_t)(g0 + la_r[it])*FF + f1 + la_c[it]]);
                rb[it] = *reinterpret_cast<const float4*>(&Bm[(size_t)(f1 + lb_r[it])*WW + w0 + lb_c[it]]);
            }
        }

        #pragma unroll
        for (int kk = 0; kk < 16; kk++) {
            float4 a0 = *reinterpret_cast<const float4*>(&As[kk][ty*8]);
            float4 a1 = *reinterpret_cast<const float4*>(&As[kk][ty*8 + 4]);
            ulonglong2 b0 = *reinterpret_cast<const ulonglong2*>(&Bs[kk][tx*8]);
            ulonglong2 b1 = *reinterpret_cast<const ulonglong2*>(&Bs[kk][tx*8 + 4]);
            ull av0 = bc2(a0.x), av1 = bc2(a0.y), av2 = bc2(a0.z), av3 = bc2(a0.w);
            ull av4 = bc2(a1.x), av5 = bc2(a1.y), av6 = bc2(a1.z), av7 = bc2(a1.w);
            fma2(acc2[0][0], av0, b0.x); fma2(acc2[0][1], av0, b0.y); fma2(acc2[0][2], av0, b1.x); fma2(acc2[0][3], av0, b1.y);
            fma2(acc2[1][0], av1, b0.x); fma2(acc2[1][1], av1, b0.y); fma2(acc2[1][2], av1, b1.x); fma2(acc2[1][3], av1, b1.y);
            fma2(acc2[2][0], av2, b0.x); fma2(acc2[2][1], av2, b0.y); fma2(acc2[2][2], av2, b1.x); fma2(acc2[2][3], av2, b1.y);
            fma2(acc2[3][0], av3, b0.x); fma2(acc2[3][1], av3, b0.y); fma2(acc2[3][2], av3, b1.x); fma2(acc2[3][3], av3, b1.y);
            fma2(acc2[4][0], av4, b0.x); fma2(acc2[4][1], av4, b0.y); fma2(acc2[4][2], av4, b1.x); fma2(acc2[4][3], av4, b1.y);
            fma2(acc2[5][0], av5, b0.x); fma2(acc2[5][1], av5, b0.y); fma2(acc2[5][2], av5, b1.x); fma2(acc2[5][3], av5, b1.y);
            fma2(acc2[6][0], av6, b0.x); fma2(acc2[6][1], av6, b0.y); fma2(acc2[6][2], av6, b1.x); fma2(acc2[6][3], av6, b1.y);
            fma2(acc2[7][0], av7, b0.x); fma2(acc2[7][1], av7, b0.y); fma2(acc2[7][2], av7, b1.x); fma2(acc2[7][3], av7, b1.y);
        }
    }

    #pragma unroll
    for (int i = 0; i < 8; i++) {
        int g = g0 + ty*8 + i;
        float r_[8];
        #pragma unroll
        for (int j = 0; j < 4; j++) {
            float2 f2 = up2(acc2[i][j]);
            r_[2*j] = f2.x; r_[2*j+1] = f2.y;
        }
        float* op = &Out[(size_t)g*WW + w0 + tx*8];
        *reinterpret_cast<float4*>(op)     = make_float4(r_[0], r_[1], r_[2], r_[3]);
        *reinterpret_cast<float4*>(op + 4) = make_float4(r_[4], r_[5], r_[6], r_[7]);
    }
}

// =====================================================================
// K5b: depthwise channel mix (float4)
// =====================================================================
__global__ __launch_bounds__(256)
void mix_kernel(const float* __restrict__ o_dw, float* __restrict__ out)
{
    int idx = blockIdx.x * 256 + threadIdx.x;
    int b   = idx / (FF*WW/4);
    int gw4 = idx % (FF*WW/4);

    __shared__ float sdw[CH*CA];
    if (threadIdx.x < CH*CA) sdw[threadIdx.x] = o_dw[threadIdx.x];
    __syncthreads();

    float4 vc[CA];
    #pragma unroll
    for (int c = 0; c < CA; c++)
        vc[c] = *reinterpret_cast<const float4*>(&g_o1[(size_t)(b*CA + c)*FF*WW + gw4*4]);

    #pragma unroll
    for (int d = 0; d < CH; d++) {
        float4 s = make_float4(0.f, 0.f, 0.f, 0.f);
        #pragma unroll
        for (int c = 0; c < CA; c++) {
            float wdc = sdw[d*CA + c];
            s.x = fmaf(wdc, vc[c].x, s.x);
            s.y = fmaf(wdc, vc[c].y, s.y);
            s.z = fmaf(wdc, vc[c].z, s.z);
            s.w = fmaf(wdc, vc[c].w, s.w);
        }
        *reinterpret_cast<float4*>(&out[(size_t)(b*CH + d)*FF*WW + gw4*4]) = s;
    }
}

// =====================================================================
extern "C" void kernel_launch(void* const* d_in, const int* in_sizes, int n_in,
                              void* d_out, int out_size)
{
    const float* x       = (const float*)d_in[0];
    const float* prev_qk = (const float*)d_in[1];
    const float* q_pw = (const float*)d_in[4];
    const float* k_pw = (const float*)d_in[7];
    const float* v_pw = (const float*)d_in[10];
    const float* o_pw = (const float*)d_in[11];
    const float* o_dw = (const float*)d_in[12];

    cudaMemcpyToSymbolAsync(c_qcw, d_in[2], AM*CH*9*sizeof(float), 0, cudaMemcpyDeviceToDevice);
    cudaMemcpyToSymbolAsync(c_qcb, d_in[3], AM*sizeof(float),      0, cudaMemcpyDeviceToDevice);
    cudaMemcpyToSymbolAsync(c_kcw, d_in[5], AM*CH*9*sizeof(float), 0, cudaMemcpyDeviceToDevice);
    cudaMemcpyToSymbolAsync(c_kcb, d_in[6], AM*sizeof(float),      0, cudaMemcpyDeviceToDevice);
    cudaMemcpyToSymbolAsync(c_vcw, d_in[8], AM*CH*9*sizeof(float), 0, cudaMemcpyDeviceToDevice);
    cudaMemcpyToSymbolAsync(c_vcb, d_in[9], AM*sizeof(float),      0, cudaMemcpyDeviceToDevice);

    static bool attr_set = false;
    if (!attr_set) {
        cudaFuncSetAttribute(flash_kernel, cudaFuncAttributeMaxDynamicSharedMemorySize, FL_SMEM);
        attr_set = true;
    }

    float* out_main = (float*)d_out;                  // (B,CH,F,W)
    float* qk_out   = (float*)d_out + OUT_ELEMS;      // (B,AM,NH,W,W)

    cs_init_kernel<<<dim3((16*WW + 255)/256), 256>>>();
    conv_kernel<<<dim3(FF, BB*AM), 384>>>(x);
    pw_kernel<<<dim3(FF/128, WW/128, 3*BB*AM), 256>>>(q_pw, k_pw, v_pw);
    flash_kernel<<<dim3(WW/128, BB*AM*NHH), 256, FL_SMEM>>>(prev_qk, qk_out);
    opw_kernel<<<dim3(FF/128, WW/128, BB*CA), 256>>>(x, o_pw);
    mix_kernel<<<dim3(BB*FF*WW/1024), 256>>>(o_dw, out_main);
}